// round 11
// baseline (speedup 1.0000x reference)
#include <cuda_runtime.h>
#include <cuda_bf16.h>

// Contamination: out = 0.8*x + 0.2 * avg(valid neighbors at {-8,0,8}^2 \ {0,0})
// x: [B=8, C=32, H=512, W=512] fp32, k=8.
//
// R11: FULL-row prefetch pipeline. R9/R10 prefetched only the next-row center;
// the side loads (c4 +/- 2) touch one 128B line OUTSIDE the warp's prefetched
// window (owned by the x-adjacent CTA on another SM) -> L1-miss/L2-hit
// (~250cyc) consumed same-iteration, stalling every warp every iteration.
// Here each iteration loads center+sides of row h+2K and folds them into a
// depth-2 sum roll (Sprev/Scur/Snext + centers Ccur/Cnext): no load is
// consumed in its issue iteration. 32-row tiles (L2-footprint-safe, R6),
// streaming stores. lb(256,6): ~42-reg budget for the wider roll, 48 warps.

namespace {

constexpr int H  = 512;
constexpr int W  = 512;
constexpr int K  = 8;
constexpr int W4 = W / 4;       // 128 float4 per row

__device__ __forceinline__ float4 f4zero() { return make_float4(0.f, 0.f, 0.f, 0.f); }

__device__ __forceinline__ float4 f4add(float4 a, float4 b) {
    return make_float4(a.x + b.x, a.y + b.y, a.z + b.z, a.w + b.w);
}

__global__ __launch_bounds__(256, 6)
void contam_kernel(const float4* __restrict__ in, float4* __restrict__ out) {
    const int c4   = blockIdx.x * 32 + threadIdx.x;   // float4 column, 0..127
    const int row0 = blockIdx.y * 32 + threadIdx.y;   // first output row (<=487)
    const int plane = blockIdx.z;

    const float4* __restrict__ pin  = in  + (size_t)plane * (H * W4);
    float4* __restrict__       pout = out + (size_t)plane * (H * W4);

    const bool hasL = (c4 >= 2);
    const bool hasR = (c4 <= W4 - 3);
    const int  nc   = 1 + (int)hasL + (int)hasR;

    // ---- prologue: rows row0-K (sum), row0 (sum+center), row0+K (sum+center) ----
    float4 Sprev = f4zero();
    if (row0 >= K) {
        const float4* __restrict__ r = pin + (row0 - K) * W4;
        Sprev = r[c4];
        if (hasL) Sprev = f4add(Sprev, r[c4 - 2]);
        if (hasR) Sprev = f4add(Sprev, r[c4 + 2]);
    }
    float4 Ccur, Scur;
    {
        const float4* __restrict__ r = pin + row0 * W4;
        Ccur = r[c4];
        Scur = Ccur;
        if (hasL) Scur = f4add(Scur, r[c4 - 2]);
        if (hasR) Scur = f4add(Scur, r[c4 + 2]);
    }
    float4 Cnext, Snext;
    {
        // row0+K <= 495: always valid
        const float4* __restrict__ r = pin + (row0 + K) * W4;
        Cnext = r[c4];
        Snext = Cnext;
        if (hasL) Snext = f4add(Snext, r[c4 - 2]);
        if (hasR) Snext = f4add(Snext, r[c4 + 2]);
    }

    #pragma unroll
    for (int ry = 0; ry < 4; ry++) {
        const int h    = row0 + ry * K;
        const bool vn  = (h + K < H);          // row h+K valid (neighbor of h)
        const int rn2  = h + 2 * K;
        const bool vn2 = (rn2 < H);
        const int rn2c = vn2 ? rn2 : h;        // clamped legal address

        // ---- prefetch FULL row h+2K (center + sides), consumed next iter ----
        const float4* __restrict__ rowP = pin + rn2c * W4;
        float4 n1 = rowP[c4];
        float4 n0 = hasL ? rowP[c4 - 2] : f4zero();
        float4 n2 = hasR ? rowP[c4 + 2] : f4zero();
        float4 S2 = vn2 ? f4add(f4add(n1, n0), n2) : f4zero();

        const int nr = 1 + (int)(h >= K) + (int)vn;
        // count = nr*nc - 1 in {3,5,8}  <=>  nr+nc in {4,5,6}
        const int s  = nr + nc;
        const float scale = (s == 6) ? 0.025f
                          : (s == 5) ? 0.04f
                                     : 0.066666667f;
        const float a = 0.8f - scale;

        // acc includes Ccur (inside Scur): out = (0.8-scale)*Ccur + scale*acc.
        // Snext is pre-zeroed when row h+K invalid.
        float4 acc = f4add(f4add(Sprev, Scur), vn ? Snext : f4zero());

        float4 o;
        o.x = a * Ccur.x + scale * acc.x;
        o.y = a * Ccur.y + scale * acc.y;
        o.z = a * Ccur.z + scale * acc.z;
        o.w = a * Ccur.w + scale * acc.w;

        __stcs(&pout[h * W4 + c4], o);

        // roll forward one K-row
        Sprev = Scur;
        Scur  = Snext;
        Snext = S2;
        Ccur  = Cnext;
        Cnext = n1;
    }
}

} // namespace

extern "C" void kernel_launch(void* const* d_in, const int* in_sizes, int n_in,
                              void* d_out, int out_size) {
    const float4* x = (const float4*)d_in[0];
    float4* out = (float4*)d_out;

    const int planes = in_sizes[0] / (H * W);   // 256

    dim3 block(32, 8, 1);
    dim3 grid(W4 / 32, H / 32, planes);         // (4, 16, 256)
    contam_kernel<<<grid, block>>>(x, out);
}